// round 1
// baseline (speedup 1.0000x reference)
#include <cuda_runtime.h>
#include <stdint.h>

// Fp8Unpadding: gather un-padded rows out of a 256-row-padded concatenation.
// M_SPLITS = {1000,2300,512,3777,129,2048,900,1500}, HIDDEN=4096 (f32).
// dst row r in group g maps to src row r + DELTA[g]; DELTA constant per group.
//
// Row boundaries (cumulative m):  1000, 3300, 3812, 7589, 7718, 9766, 10666, 12166
// Row deltas (padded_off-dst_off):   0,   24,   28,   28,   91,  218,   218,   342
// Groups 2/3 and 5/6 share deltas -> 5 comparisons suffice.

static constexpr int HIDDEN_V4   = 4096 / 4;          // 1024 float4 per row
static constexpr int TOTAL_ROWS  = 12166;             // sum(M_SPLITS)
static constexpr int TOTAL_V4    = TOTAL_ROWS * HIDDEN_V4;  // 12,457,984

__global__ void __launch_bounds__(256)
unpad_gather_kernel(const float4* __restrict__ in, float4* __restrict__ out)
{
    int i = blockIdx.x * blockDim.x + threadIdx.x;
    if (i >= TOTAL_V4) return;

    int row = i >> 10;  // i / 1024

    // per-group constant source-row delta
    int d = (row < 1000)  ? 0
          : (row < 3300)  ? 24
          : (row < 7589)  ? 28
          : (row < 7718)  ? 91
          : (row < 10666) ? 218
          :                 342;

    out[i] = in[i + d * HIDDEN_V4];
}

extern "C" void kernel_launch(void* const* d_in, const int* in_sizes, int n_in,
                              void* d_out, int out_size)
{
    const float4* in  = (const float4*)d_in[0];   // f32 [12544, 4096]
    float4*       out = (float4*)d_out;           // f32 [12166, 4096]

    int blocks = (TOTAL_V4 + 255) / 256;
    unpad_gather_kernel<<<blocks, 256>>>(in, out);
}

// round 2
// speedup vs baseline: 1.0056x; 1.0056x over previous
#include <cuda_runtime.h>
#include <stdint.h>

// Fp8Unpadding: gather un-padded rows out of a 256-row-padded concatenation.
// M_SPLITS = {1000,2300,512,3777,129,2048,900,1500}, HIDDEN=4096 (f32).
// dst row r maps to src row r + DELTA[group(r)]; DELTA constant per group.
//
// Row boundaries (cumulative m):  1000, 3300, 3812, 7589, 7718, 9766, 10666, 12166
// Row deltas:                        0,   24,   28,   28,   91,  218,   218,   342
//
// R2: 8x float4 per thread, front-batched loads (MLP=8/thread), streaming
// cache hints (no reuse, don't thrash L2). 12,457,984 v4 = 6083 * 2048 exactly
// -> no tail, no bounds check.

static constexpr int HIDDEN_V4  = 4096 / 4;                 // 1024
static constexpr int TOTAL_ROWS = 12166;
static constexpr int TOTAL_V4   = TOTAL_ROWS * HIDDEN_V4;   // 12,457,984
static constexpr int UNROLL     = 8;
static constexpr int TPB        = 256;
static constexpr int PER_BLOCK  = TPB * UNROLL;             // 2048
static constexpr int NBLOCKS    = TOTAL_V4 / PER_BLOCK;     // 6083 (exact)

__device__ __forceinline__ int row_delta(int row)
{
    return (row < 1000)  ? 0
         : (row < 3300)  ? 24
         : (row < 7589)  ? 28
         : (row < 7718)  ? 91
         : (row < 10666) ? 218
         :                 342;
}

__global__ void __launch_bounds__(TPB)
unpad_gather_kernel(const float4* __restrict__ in, float4* __restrict__ out)
{
    int base = blockIdx.x * PER_BLOCK + threadIdx.x;

    float4 v[UNROLL];

    // front-batched independent loads (deep MLP)
    #pragma unroll
    for (int j = 0; j < UNROLL; j++) {
        int i = base + j * TPB;
        int d = row_delta(i >> 10);
        v[j] = __ldcs(in + i + d * HIDDEN_V4);
    }

    // stores
    #pragma unroll
    for (int j = 0; j < UNROLL; j++) {
        int i = base + j * TPB;
        __stcs(out + i, v[j]);
    }
}

extern "C" void kernel_launch(void* const* d_in, const int* in_sizes, int n_in,
                              void* d_out, int out_size)
{
    const float4* in  = (const float4*)d_in[0];   // f32 [12544, 4096]
    float4*       out = (float4*)d_out;           // f32 [12166, 4096]

    unpad_gather_kernel<<<NBLOCKS, TPB>>>(in, out);
}